// round 16
// baseline (speedup 1.0000x reference)
#include <cuda_runtime.h>
#include <cuda_fp16.h>
#include <cstdint>

// ============================================================================
// Problem constants
// ============================================================================
#define B_TOTAL   16384
#define F_FEAT    64
#define H_DIM     64
#define ROWS_PER_CTA 256     // 8 warps * 32 rows
#define ROWBLKS   (B_TOTAL / ROWS_PER_CTA)   // 64
#define GRID_MAIN (F_FEAT * ROWBLKS)         // 4096

// PDL primitives (sm_90+)
__device__ __forceinline__ void pdl_trigger() {
    asm volatile("griddepcontrol.launch_dependents;" ::: "memory");
}
__device__ __forceinline__ void pdl_wait() {
    asm volatile("griddepcontrol.wait;" ::: "memory");
}

// ============================================================================
// Device scratch (no allocation allowed)
// ============================================================================
// Weights pre-arranged in mma.sync B-fragment order, single fp16 plane:
// [l][f][kt(4)][nt(8)][lane(32)] of uint2 (reg0, reg1) -> 1 MB
__device__ __align__(16) uint2 g_wfrag[2 * F_FEAT * 4 * 8 * 32];
// Per-feature contributions g_feat[f][b] -> 4 MB
__device__ float g_feat[F_FEAT * B_TOTAL];

// ============================================================================
// mma.sync m16n8k16 fp16, fp32 accumulate (sm_80+, valid on plain sm_100)
// ============================================================================
__device__ __forceinline__ void mma_f16(float c[4], const uint32_t a[4],
                                        uint32_t b0, uint32_t b1) {
    asm("mma.sync.aligned.m16n8k16.row.col.f32.f16.f16.f32 "
        "{%0,%1,%2,%3}, {%4,%5,%6,%7}, {%8,%9}, {%0,%1,%2,%3};"
        : "+f"(c[0]), "+f"(c[1]), "+f"(c[2]), "+f"(c[3])
        : "r"(a[0]), "r"(a[1]), "r"(a[2]), "r"(a[3]), "r"(b0), "r"(b1));
}

// relu both, pack to fp16x2 (low 16 bits = e0).
__device__ __forceinline__ uint32_t relu_pack(float e0, float e1) {
    __half2 h = __floats2half2_rn(fmaxf(e0, 0.0f), fmaxf(e1, 0.0f));
    return *reinterpret_cast<uint32_t*>(&h);
}

// ============================================================================
// Kernel 1: rearrange w_hid [l][f][k][n] f32 -> fp16 B-fragment layout.
// Coalesced rewrite: one CTA per (l,f) 64x64 tile; gmem->smem streaming load,
// then fragment gather from smem, contiguous coalesced stores.
// Output values/layout bit-identical to the previous prep kernel.
// ============================================================================
__global__ void __launch_bounds__(256) nam_prep_kernel(const float* __restrict__ w_hid) {
    __shared__ float s_w[H_DIM * H_DIM];   // [k][n], 16 KB

    const int tid = threadIdx.x;
    const int lf  = blockIdx.x;            // l*F_FEAT + f, [0,128)

    // ---- coalesced tile load: 4096 floats = 256 threads x 4 float4 ----
    const float4* src = reinterpret_cast<const float4*>(w_hid + (long)lf * H_DIM * H_DIM);
    float4* dst = reinterpret_cast<float4*>(s_w);
    #pragma unroll
    for (int it = 0; it < 4; ++it)
        dst[it * 256 + tid] = src[it * 256 + tid];
    __syncthreads();

    // ---- fragment build: 1024 uint2 per tile = 256 threads x 4 ----
    uint2* outp = g_wfrag + ((long)lf << 10);
    #pragma unroll
    for (int j = 0; j < 4; ++j) {
        int i  = j * 256 + tid;            // [0, 1024): kt*256 + nt*32 + t
        int t  = i & 31;
        int nt = (i >> 5) & 7;
        int kt = i >> 8;

        int n  = nt * 8 + (t >> 2);
        int k0 = kt * 16 + 2 * (t & 3);
        float w00 = s_w[(k0    ) * H_DIM + n];
        float w01 = s_w[(k0 + 1) * H_DIM + n];
        float w10 = s_w[(k0 + 8) * H_DIM + n];
        float w11 = s_w[(k0 + 9) * H_DIM + n];

        __half2 p0 = __floats2half2_rn(w00, w01);   // low = k0
        __half2 p1 = __floats2half2_rn(w10, w11);   // low = k0+8
        uint2 o;
        o.x = *reinterpret_cast<uint32_t*>(&p0);
        o.y = *reinterpret_cast<uint32_t*>(&p1);
        outp[i] = o;                       // consecutive tid -> coalesced
    }

    pdl_trigger();
}

// ============================================================================
// Kernel 2: main (exact R12 body; PDL wait at entry, trigger at exit).
// CTA = (feature f, 256-row block). 8 warps, each warp owns 32 rows (m=2).
// Single-pass fp16 mma.sync, fp32 accumulate, bias folded into acc init.
// ============================================================================
__global__ void __launch_bounds__(256)
nam_main_kernel(const float* __restrict__ x,
                const float* __restrict__ w_in,
                const float* __restrict__ b_in,
                const float* __restrict__ b_hid,
                const float* __restrict__ w_out,
                const float* __restrict__ b_out,
                const float* __restrict__ w_final)
{
    __shared__ __align__(16) uint2 s_wfrag[2 * 1024];   // [l][kt*8+nt][lane], 16 KB
    __shared__ float s_win[H_DIM], s_bin[H_DIM];
    __shared__ float s_bh[2][H_DIM];
    __shared__ float s_wout[H_DIM];

    pdl_wait();   // g_wfrag must be complete before staging

    const int tid  = threadIdx.x;
    const int lane = tid & 31;
    const int warp = tid >> 5;
    const int f  = blockIdx.x >> 6;
    const int rb = blockIdx.x & 63;
    const int rowbase = rb * ROWS_PER_CTA + warp * 32;

    // ---- stage weights (B-frag order) + per-feature params into smem ----
    {
        uint4* dst = reinterpret_cast<uint4*>(s_wfrag);
        #pragma unroll
        for (int it = 0; it < 4; ++it) {
            int j = it * 256 + tid;          // [0, 1024)
            int l   = j >> 9;
            int rem = j & 511;
            dst[j] = reinterpret_cast<const uint4*>(g_wfrag)
                        [(((long)(l * F_FEAT + f)) << 9) + rem];
        }
    }
    if (tid < 64) {
        s_win[tid]   = __ldg(&w_in[f * 64 + tid]);
        s_bin[tid]   = __ldg(&b_in[f * 64 + tid]);
        s_bh[0][tid] = __ldg(&b_hid[(0 * F_FEAT + f) * 64 + tid]);
        s_bh[1][tid] = __ldg(&b_hid[(1 * F_FEAT + f) * 64 + tid]);
        s_wout[tid]  = __ldg(&w_out[f * 64 + tid]);
    }
    __syncthreads();

    const int q = lane & 3;     // quad index -> col pair
    const int g = lane >> 2;    // group row

    const float wf = __ldg(&w_final[f]);
    const float bo = __ldg(&b_out[f]);

    // ---- input layer: h0 = relu(x * w_in + b_in), built directly in A-frag layout
    float xs[2][2];
    #pragma unroll
    for (int m = 0; m < 2; ++m)
        #pragma unroll
        for (int s = 0; s < 2; ++s)
            xs[m][s] = __ldg(&x[(rowbase + m * 16 + g + s * 8) * F_FEAT + f]);

    uint32_t A[2][4][4];
    #pragma unroll
    for (int kt = 0; kt < 4; ++kt) {
        #pragma unroll
        for (int p = 0; p < 2; ++p) {
            const int c0 = kt * 16 + 2 * q + p * 8;
            const float w0 = s_win[c0], w1 = s_win[c0 + 1];
            const float bb0 = s_bin[c0], bb1 = s_bin[c0 + 1];
            #pragma unroll
            for (int m = 0; m < 2; ++m)
                #pragma unroll
                for (int s = 0; s < 2; ++s) {
                    float e0 = fmaf(xs[m][s], w0, bb0);
                    float e1 = fmaf(xs[m][s], w1, bb1);
                    A[m][kt][2 * p + s] = relu_pack(e0, e1);
                }
        }
    }

    // ---- hidden layers ----
    float acc[2][8][4];
    #pragma unroll 2
    for (int l = 0; l < 2; ++l) {
        // init accumulators with bias (mma accumulates on top)
        #pragma unroll
        for (int nt = 0; nt < 8; ++nt) {
            float bb0 = s_bh[l][nt * 8 + 2 * q];
            float bb1 = s_bh[l][nt * 8 + 2 * q + 1];
            #pragma unroll
            for (int m = 0; m < 2; ++m) {
                acc[m][nt][0] = bb0; acc[m][nt][1] = bb1;
                acc[m][nt][2] = bb0; acc[m][nt][3] = bb1;
            }
        }

        const uint2* b_ptr = s_wfrag + l * 1024;

        #pragma unroll
        for (int kt = 0; kt < 4; ++kt) {
            #pragma unroll
            for (int nt = 0; nt < 8; ++nt) {
                uint2 bh = b_ptr[(kt * 8 + nt) * 32 + lane];
                mma_f16(acc[0][nt], A[0][kt], bh.x, bh.y);
                mma_f16(acc[1][nt], A[1][kt], bh.x, bh.y);
            }
        }

        if (l == 0) {
            // relu + pack, C-frags -> next layer's A-frags
            #pragma unroll
            for (int m = 0; m < 2; ++m)
                #pragma unroll
                for (int kt = 0; kt < 4; ++kt) {
                    A[m][kt][0] = relu_pack(acc[m][2*kt  ][0], acc[m][2*kt  ][1]);
                    A[m][kt][1] = relu_pack(acc[m][2*kt  ][2], acc[m][2*kt  ][3]);
                    A[m][kt][2] = relu_pack(acc[m][2*kt+1][0], acc[m][2*kt+1][1]);
                    A[m][kt][3] = relu_pack(acc[m][2*kt+1][2], acc[m][2*kt+1][3]);
                }
        }
    }

    // ---- output layer: feat = relu(h2) . w_out + b_out; contribution *= w_final
    float pr[2][2] = {{0.f, 0.f}, {0.f, 0.f}};   // [m][s]
    #pragma unroll
    for (int m = 0; m < 2; ++m)
        #pragma unroll
        for (int nt = 0; nt < 8; ++nt) {
            const int c0 = nt * 8 + 2 * q;
            const float w0 = s_wout[c0], w1 = s_wout[c0 + 1];
            pr[m][0] = fmaf(fmaxf(acc[m][nt][0], 0.f), w0, pr[m][0]);
            pr[m][0] = fmaf(fmaxf(acc[m][nt][1], 0.f), w1, pr[m][0]);
            pr[m][1] = fmaf(fmaxf(acc[m][nt][2], 0.f), w0, pr[m][1]);
            pr[m][1] = fmaf(fmaxf(acc[m][nt][3], 0.f), w1, pr[m][1]);
        }
    // reduce across the 4 lanes of each quad-group (cols)
    #pragma unroll
    for (int m = 0; m < 2; ++m)
        #pragma unroll
        for (int s = 0; s < 2; ++s) {
            float v = pr[m][s];
            v += __shfl_xor_sync(0xffffffffu, v, 1);
            v += __shfl_xor_sync(0xffffffffu, v, 2);
            pr[m][s] = v;
        }
    if (q == 0) {
        #pragma unroll
        for (int m = 0; m < 2; ++m) {
            int row0 = rowbase + m * 16 + g;
            g_feat[f * B_TOTAL + row0]     = (pr[m][0] + bo) * wf;
            g_feat[f * B_TOTAL + row0 + 8] = (pr[m][1] + bo) * wf;
        }
    }

    pdl_trigger();
}

// ============================================================================
// Kernel 3: reduce over features + sigmoid. 4 threads per row (16 contiguous
// features each -> deterministic order) + quad shfl reduce. Grid 256.
// (unchanged; PDL wait at entry)
// ============================================================================
__global__ void __launch_bounds__(256) nam_final_kernel(const float* __restrict__ b_final,
                                                        float* __restrict__ out) {
    pdl_wait();   // g_feat must be complete

    const int tid = threadIdx.x;
    const int row = blockIdx.x * 64 + (tid >> 2);
    const int fg  = (tid & 3) * 16;
    float z = 0.0f;
    #pragma unroll 16
    for (int i = 0; i < 16; ++i)
        z += g_feat[(fg + i) * B_TOTAL + row];
    z += __shfl_xor_sync(0xffffffffu, z, 1);
    z += __shfl_xor_sync(0xffffffffu, z, 2);
    if ((tid & 3) == 0)
        out[row] = 1.0f / (1.0f + expf(-(z + __ldg(&b_final[0]))));
}

// ============================================================================
// Launch (PDL: main and final launched with programmatic stream serialization)
// ============================================================================
extern "C" void kernel_launch(void* const* d_in, const int* in_sizes, int n_in,
                              void* d_out, int out_size) {
    (void)in_sizes; (void)n_in; (void)out_size;
    const float* x       = (const float*)d_in[0];
    const float* w_in    = (const float*)d_in[1];
    const float* b_in    = (const float*)d_in[2];
    const float* w_hid   = (const float*)d_in[3];
    const float* b_hid   = (const float*)d_in[4];
    const float* w_out   = (const float*)d_in[5];
    const float* b_out   = (const float*)d_in[6];
    const float* w_final = (const float*)d_in[7];
    const float* b_final = (const float*)d_in[8];
    float* out = (float*)d_out;

    nam_prep_kernel<<<2 * F_FEAT, 256>>>(w_hid);

    cudaLaunchAttribute attrs[1];
    attrs[0].id = cudaLaunchAttributeProgrammaticStreamSerialization;
    attrs[0].val.programmaticStreamSerializationAllowed = 1;

    {
        cudaLaunchConfig_t cfg = {};
        cfg.gridDim = dim3(GRID_MAIN);
        cfg.blockDim = dim3(256);
        cfg.dynamicSmemBytes = 0;
        cfg.stream = 0;
        cfg.attrs = attrs;
        cfg.numAttrs = 1;
        cudaLaunchKernelEx(&cfg, nam_main_kernel,
                           x, w_in, b_in, b_hid, w_out, b_out, w_final);
    }
    {
        cudaLaunchConfig_t cfg = {};
        cfg.gridDim = dim3(B_TOTAL / 64);
        cfg.blockDim = dim3(256);
        cfg.dynamicSmemBytes = 0;
        cfg.stream = 0;
        cfg.attrs = attrs;
        cfg.numAttrs = 1;
        cudaLaunchKernelEx(&cfg, nam_final_kernel, b_final, out);
    }
}

// round 17
// speedup vs baseline: 1.0115x; 1.0115x over previous
#include <cuda_runtime.h>
#include <cuda_fp16.h>
#include <cstdint>

// ============================================================================
// Problem constants
// ============================================================================
#define B_TOTAL   16384
#define F_FEAT    64
#define H_DIM     64
#define ROWS_PER_CTA 256     // 8 warps * 32 rows
#define ROWBLKS   (B_TOTAL / ROWS_PER_CTA)   // 64
#define GRID_MAIN (F_FEAT * ROWBLKS)         // 4096

// PDL primitives (sm_90+)
__device__ __forceinline__ void pdl_trigger() {
    asm volatile("griddepcontrol.launch_dependents;" ::: "memory");
}
__device__ __forceinline__ void pdl_wait() {
    asm volatile("griddepcontrol.wait;" ::: "memory");
}

// ============================================================================
// Device scratch (no allocation allowed)
// ============================================================================
// Weights pre-arranged in mma.sync B-fragment order, single fp16 plane:
// [l][f][kt(4)][nt(8)][lane(32)] of uint2 (reg0, reg1) -> 1 MB
__device__ __align__(16) uint2 g_wfrag[2 * F_FEAT * 4 * 8 * 32];
// Per-feature contributions g_feat[f][b] -> 4 MB
__device__ float g_feat[F_FEAT * B_TOTAL];

// ============================================================================
// mma.sync m16n8k16 fp16, fp32 accumulate (sm_80+, valid on plain sm_100)
// ============================================================================
__device__ __forceinline__ void mma_f16(float c[4], const uint32_t a[4],
                                        uint32_t b0, uint32_t b1) {
    asm("mma.sync.aligned.m16n8k16.row.col.f32.f16.f16.f32 "
        "{%0,%1,%2,%3}, {%4,%5,%6,%7}, {%8,%9}, {%0,%1,%2,%3};"
        : "+f"(c[0]), "+f"(c[1]), "+f"(c[2]), "+f"(c[3])
        : "r"(a[0]), "r"(a[1]), "r"(a[2]), "r"(a[3]), "r"(b0), "r"(b1));
}

// relu both, pack to fp16x2 (low 16 bits = e0).
__device__ __forceinline__ uint32_t relu_pack(float e0, float e1) {
    __half2 h = __floats2half2_rn(fmaxf(e0, 0.0f), fmaxf(e1, 0.0f));
    return *reinterpret_cast<uint32_t*>(&h);
}

// ============================================================================
// Kernel 1: rearrange w_hid [l][f][k][n] f32 -> fp16 B-fragment layout.
// One CTA per (l, f, kt) quarter-tile (grid 512): coalesced 4 KB strip load
// into smem, one fragment per thread, coalesced contiguous store.
// Output values/layout bit-identical to the R12 prep kernel.
// ============================================================================
__global__ void __launch_bounds__(256) nam_prep_kernel(const float* __restrict__ w_hid) {
    __shared__ float s_w[16 * H_DIM];      // k-strip [16][64], 4 KB

    const int tid = threadIdx.x;
    const int bid = blockIdx.x;            // lf*4 + kt, [0, 512)
    const int lf  = bid >> 2;
    const int kt  = bid & 3;

    // ---- coalesced strip load: 1024 floats = 256 threads x 1 float4 ----
    const float4* src = reinterpret_cast<const float4*>(
        w_hid + ((long)lf * H_DIM + kt * 16) * H_DIM);
    reinterpret_cast<float4*>(s_w)[tid] = src[tid];
    __syncthreads();

    // ---- one fragment (uint2) per thread ----
    const int t  = tid & 31;
    const int nt = tid >> 5;
    const int n  = nt * 8 + (t >> 2);
    const int k0 = 2 * (t & 3);            // local k within the strip
    float w00 = s_w[(k0    ) * H_DIM + n];
    float w01 = s_w[(k0 + 1) * H_DIM + n];
    float w10 = s_w[(k0 + 8) * H_DIM + n];
    float w11 = s_w[(k0 + 9) * H_DIM + n];

    __half2 p0 = __floats2half2_rn(w00, w01);   // low = k0
    __half2 p1 = __floats2half2_rn(w10, w11);   // low = k0+8
    uint2 o;
    o.x = *reinterpret_cast<uint32_t*>(&p0);
    o.y = *reinterpret_cast<uint32_t*>(&p1);
    // output index: lf*1024 + kt*256 + nt*32 + t == bid*256 + tid
    g_wfrag[(long)bid * 256 + tid] = o;

    pdl_trigger();
}

// ============================================================================
// Kernel 2: main (exact R12 body; PDL wait at entry, trigger at exit).
// CTA = (feature f, 256-row block). 8 warps, each warp owns 32 rows (m=2).
// Single-pass fp16 mma.sync, fp32 accumulate, bias folded into acc init.
// ============================================================================
__global__ void __launch_bounds__(256)
nam_main_kernel(const float* __restrict__ x,
                const float* __restrict__ w_in,
                const float* __restrict__ b_in,
                const float* __restrict__ b_hid,
                const float* __restrict__ w_out,
                const float* __restrict__ b_out,
                const float* __restrict__ w_final)
{
    __shared__ __align__(16) uint2 s_wfrag[2 * 1024];   // [l][kt*8+nt][lane], 16 KB
    __shared__ float s_win[H_DIM], s_bin[H_DIM];
    __shared__ float s_bh[2][H_DIM];
    __shared__ float s_wout[H_DIM];

    pdl_wait();   // g_wfrag must be complete before staging

    const int tid  = threadIdx.x;
    const int lane = tid & 31;
    const int warp = tid >> 5;
    const int f  = blockIdx.x >> 6;
    const int rb = blockIdx.x & 63;
    const int rowbase = rb * ROWS_PER_CTA + warp * 32;

    // ---- stage weights (B-frag order) + per-feature params into smem ----
    {
        uint4* dst = reinterpret_cast<uint4*>(s_wfrag);
        #pragma unroll
        for (int it = 0; it < 4; ++it) {
            int j = it * 256 + tid;          // [0, 1024)
            int l   = j >> 9;
            int rem = j & 511;
            dst[j] = reinterpret_cast<const uint4*>(g_wfrag)
                        [(((long)(l * F_FEAT + f)) << 9) + rem];
        }
    }
    if (tid < 64) {
        s_win[tid]   = __ldg(&w_in[f * 64 + tid]);
        s_bin[tid]   = __ldg(&b_in[f * 64 + tid]);
        s_bh[0][tid] = __ldg(&b_hid[(0 * F_FEAT + f) * 64 + tid]);
        s_bh[1][tid] = __ldg(&b_hid[(1 * F_FEAT + f) * 64 + tid]);
        s_wout[tid]  = __ldg(&w_out[f * 64 + tid]);
    }
    __syncthreads();

    const int q = lane & 3;     // quad index -> col pair
    const int g = lane >> 2;    // group row

    const float wf = __ldg(&w_final[f]);
    const float bo = __ldg(&b_out[f]);

    // ---- input layer: h0 = relu(x * w_in + b_in), built directly in A-frag layout
    float xs[2][2];
    #pragma unroll
    for (int m = 0; m < 2; ++m)
        #pragma unroll
        for (int s = 0; s < 2; ++s)
            xs[m][s] = __ldg(&x[(rowbase + m * 16 + g + s * 8) * F_FEAT + f]);

    uint32_t A[2][4][4];
    #pragma unroll
    for (int kt = 0; kt < 4; ++kt) {
        #pragma unroll
        for (int p = 0; p < 2; ++p) {
            const int c0 = kt * 16 + 2 * q + p * 8;
            const float w0 = s_win[c0], w1 = s_win[c0 + 1];
            const float bb0 = s_bin[c0], bb1 = s_bin[c0 + 1];
            #pragma unroll
            for (int m = 0; m < 2; ++m)
                #pragma unroll
                for (int s = 0; s < 2; ++s) {
                    float e0 = fmaf(xs[m][s], w0, bb0);
                    float e1 = fmaf(xs[m][s], w1, bb1);
                    A[m][kt][2 * p + s] = relu_pack(e0, e1);
                }
        }
    }

    // ---- hidden layers ----
    float acc[2][8][4];
    #pragma unroll 2
    for (int l = 0; l < 2; ++l) {
        // init accumulators with bias (mma accumulates on top)
        #pragma unroll
        for (int nt = 0; nt < 8; ++nt) {
            float bb0 = s_bh[l][nt * 8 + 2 * q];
            float bb1 = s_bh[l][nt * 8 + 2 * q + 1];
            #pragma unroll
            for (int m = 0; m < 2; ++m) {
                acc[m][nt][0] = bb0; acc[m][nt][1] = bb1;
                acc[m][nt][2] = bb0; acc[m][nt][3] = bb1;
            }
        }

        const uint2* b_ptr = s_wfrag + l * 1024;

        #pragma unroll
        for (int kt = 0; kt < 4; ++kt) {
            #pragma unroll
            for (int nt = 0; nt < 8; ++nt) {
                uint2 bh = b_ptr[(kt * 8 + nt) * 32 + lane];
                mma_f16(acc[0][nt], A[0][kt], bh.x, bh.y);
                mma_f16(acc[1][nt], A[1][kt], bh.x, bh.y);
            }
        }

        if (l == 0) {
            // relu + pack, C-frags -> next layer's A-frags
            #pragma unroll
            for (int m = 0; m < 2; ++m)
                #pragma unroll
                for (int kt = 0; kt < 4; ++kt) {
                    A[m][kt][0] = relu_pack(acc[m][2*kt  ][0], acc[m][2*kt  ][1]);
                    A[m][kt][1] = relu_pack(acc[m][2*kt  ][2], acc[m][2*kt  ][3]);
                    A[m][kt][2] = relu_pack(acc[m][2*kt+1][0], acc[m][2*kt+1][1]);
                    A[m][kt][3] = relu_pack(acc[m][2*kt+1][2], acc[m][2*kt+1][3]);
                }
        }
    }

    // ---- output layer: feat = relu(h2) . w_out + b_out; contribution *= w_final
    float pr[2][2] = {{0.f, 0.f}, {0.f, 0.f}};   // [m][s]
    #pragma unroll
    for (int m = 0; m < 2; ++m)
        #pragma unroll
        for (int nt = 0; nt < 8; ++nt) {
            const int c0 = nt * 8 + 2 * q;
            const float w0 = s_wout[c0], w1 = s_wout[c0 + 1];
            pr[m][0] = fmaf(fmaxf(acc[m][nt][0], 0.f), w0, pr[m][0]);
            pr[m][0] = fmaf(fmaxf(acc[m][nt][1], 0.f), w1, pr[m][0]);
            pr[m][1] = fmaf(fmaxf(acc[m][nt][2], 0.f), w0, pr[m][1]);
            pr[m][1] = fmaf(fmaxf(acc[m][nt][3], 0.f), w1, pr[m][1]);
        }
    // reduce across the 4 lanes of each quad-group (cols)
    #pragma unroll
    for (int m = 0; m < 2; ++m)
        #pragma unroll
        for (int s = 0; s < 2; ++s) {
            float v = pr[m][s];
            v += __shfl_xor_sync(0xffffffffu, v, 1);
            v += __shfl_xor_sync(0xffffffffu, v, 2);
            pr[m][s] = v;
        }
    if (q == 0) {
        #pragma unroll
        for (int m = 0; m < 2; ++m) {
            int row0 = rowbase + m * 16 + g;
            g_feat[f * B_TOTAL + row0]     = (pr[m][0] + bo) * wf;
            g_feat[f * B_TOTAL + row0 + 8] = (pr[m][1] + bo) * wf;
        }
    }

    pdl_trigger();
}

// ============================================================================
// Kernel 3: reduce over features + sigmoid. 4 threads per row (16 contiguous
// features each -> deterministic order) + quad shfl reduce. Grid 256.
// (unchanged; PDL wait at entry)
// ============================================================================
__global__ void __launch_bounds__(256) nam_final_kernel(const float* __restrict__ b_final,
                                                        float* __restrict__ out) {
    pdl_wait();   // g_feat must be complete

    const int tid = threadIdx.x;
    const int row = blockIdx.x * 64 + (tid >> 2);
    const int fg  = (tid & 3) * 16;
    float z = 0.0f;
    #pragma unroll 16
    for (int i = 0; i < 16; ++i)
        z += g_feat[(fg + i) * B_TOTAL + row];
    z += __shfl_xor_sync(0xffffffffu, z, 1);
    z += __shfl_xor_sync(0xffffffffu, z, 2);
    if ((tid & 3) == 0)
        out[row] = 1.0f / (1.0f + expf(-(z + __ldg(&b_final[0]))));
}

// ============================================================================
// Launch (PDL: main and final launched with programmatic stream serialization)
// ============================================================================
extern "C" void kernel_launch(void* const* d_in, const int* in_sizes, int n_in,
                              void* d_out, int out_size) {
    (void)in_sizes; (void)n_in; (void)out_size;
    const float* x       = (const float*)d_in[0];
    const float* w_in    = (const float*)d_in[1];
    const float* b_in    = (const float*)d_in[2];
    const float* w_hid   = (const float*)d_in[3];
    const float* b_hid   = (const float*)d_in[4];
    const float* w_out   = (const float*)d_in[5];
    const float* b_out   = (const float*)d_in[6];
    const float* w_final = (const float*)d_in[7];
    const float* b_final = (const float*)d_in[8];
    float* out = (float*)d_out;

    nam_prep_kernel<<<512, 256>>>(w_hid);

    cudaLaunchAttribute attrs[1];
    attrs[0].id = cudaLaunchAttributeProgrammaticStreamSerialization;
    attrs[0].val.programmaticStreamSerializationAllowed = 1;

    {
        cudaLaunchConfig_t cfg = {};
        cfg.gridDim = dim3(GRID_MAIN);
        cfg.blockDim = dim3(256);
        cfg.dynamicSmemBytes = 0;
        cfg.stream = 0;
        cfg.attrs = attrs;
        cfg.numAttrs = 1;
        cudaLaunchKernelEx(&cfg, nam_main_kernel,
                           x, w_in, b_in, b_hid, w_out, b_out, w_final);
    }
    {
        cudaLaunchConfig_t cfg = {};
        cfg.gridDim = dim3(B_TOTAL / 64);
        cfg.blockDim = dim3(256);
        cfg.dynamicSmemBytes = 0;
        cfg.stream = 0;
        cfg.attrs = attrs;
        cfg.numAttrs = 1;
        cudaLaunchKernelEx(&cfg, nam_final_kernel, b_final, out);
    }
}